// round 9
// baseline (speedup 1.0000x reference)
#include <cuda_runtime.h>
#include <math.h>

// Problem constants
#define Bv 4
#define Sv 2048
#define Dv 1024
#define Ev 8
#define Hv 2048
#define Tv (Bv*Sv)        // 8192 tokens
#define Av (2*Tv)         // 16384 assignments (top_k = 2)

// GEMM tiling
#define BM 128
#define BN 128
#define BK 32
#define LDAW 36           // words per A row (144B, 16B-aligned, conflict-free)
#define LDBW 136          // words per B row (mod 32 == 8 -> conflict-free frag LDS)
#define NSTAGE 3

#define STAGE_A_BYTES (BM*LDAW*4)              // 18432
#define STAGE_B_BYTES (BK*LDBW*4)              // 17408
#define STAGE_BYTES   (STAGE_A_BYTES + STAGE_B_BYTES)  // 35840
#define SMEM_TOTAL    (NSTAGE*STAGE_BYTES)     // 107520

// Device scratch (static allocations; no cudaMalloc allowed)
__device__ int   g_count[Ev];
__device__ int   g_list[Ev*Tv];           // assignment ids per expert
__device__ int   g_exp[Av];               // expert per assignment
__device__ float g_w[Av];                 // combine weight per assignment
__device__ float g_h[(size_t)Av*Hv];      // tf32-rounded gelu(FFN1), 134 MB
__device__ float g_y[(size_t)Av*Dv];      // weighted FFN2 outputs, 67 MB
__device__ float g_xt[(size_t)Tv*Dv];     // tf32-rounded x, 32 MB
__device__ float g_w1t[(size_t)Ev*Dv*Hv]; // tf32-rounded W1, 64 MB
__device__ float g_w2t[(size_t)Ev*Hv*Dv]; // tf32-rounded W2, 64 MB

__global__ void k_zero() {
    if (threadIdx.x < Ev) g_count[threadIdx.x] = 0;
}

__device__ __forceinline__ float f2tf_f(float f) {
    unsigned u;
    asm("cvt.rna.tf32.f32 %0, %1;" : "=r"(u) : "f"(f));
    return __uint_as_float(u);
}

// Round fp32 array to tf32-valued fp32 (low 13 mantissa bits cleared, rna).
__global__ void k_cvt(const float* __restrict__ src, float* __restrict__ dst) {
    int i = blockIdx.x * blockDim.x + threadIdx.x;
    float4 v = ((const float4*)src)[i];
    v.x = f2tf_f(v.x); v.y = f2tf_f(v.y); v.z = f2tf_f(v.z); v.w = f2tf_f(v.w);
    ((float4*)dst)[i] = v;
}

// Gating: one warp per token. logits = x @ Wg + bg; top-2; normalized weights.
__global__ void k_gate(const float* __restrict__ x,
                       const float* __restrict__ Wg,
                       const float* __restrict__ bg) {
    int warp = threadIdx.x >> 5, lane = threadIdx.x & 31;
    int t = blockIdx.x * 8 + warp;
    if (t >= Tv) return;
    float acc[Ev];
#pragma unroll
    for (int e = 0; e < Ev; e++) acc[e] = 0.f;
    const float* xr = x + (size_t)t * Dv;
    for (int d = lane; d < Dv; d += 32) {
        float xv = xr[d];
        const float* wr = Wg + d * Ev;
#pragma unroll
        for (int e = 0; e < Ev; e++) acc[e] += xv * __ldg(wr + e);
    }
#pragma unroll
    for (int e = 0; e < Ev; e++) {
#pragma unroll
        for (int o = 16; o > 0; o >>= 1)
            acc[e] += __shfl_xor_sync(0xffffffffu, acc[e], o);
    }
    if (lane == 0) {
        float l[Ev];
#pragma unroll
        for (int e = 0; e < Ev; e++) l[e] = acc[e] + bg[e];
        int e0 = 0;
#pragma unroll
        for (int e = 1; e < Ev; e++) if (l[e] > l[e0]) e0 = e;
        int e1 = (e0 == 0) ? 1 : 0;
#pragma unroll
        for (int e = 0; e < Ev; e++) if (e != e0 && l[e] > l[e1]) e1 = e;
        float w0 = 1.f / (1.f + expf(l[e1] - l[e0]));
        float w1 = 1.f - w0;
        int a0 = 2 * t, a1 = 2 * t + 1;
        g_exp[a0] = e0; g_exp[a1] = e1;
        g_w[a0] = w0;   g_w[a1] = w1;
        int s0 = atomicAdd(&g_count[e0], 1); g_list[e0 * Tv + s0] = a0;
        int s1 = atomicAdd(&g_count[e1], 1); g_list[e1 * Tv + s1] = a1;
    }
}

__device__ __forceinline__ float gelu_tanh(float v) {
    float u = 0.7978845608028654f * (v + 0.044715f * v * v * v);
    float th;
    asm("tanh.approx.f32 %0, %1;" : "=f"(th) : "f"(u));
    return 0.5f * v * (1.f + th);
}

__device__ __forceinline__ void mma_tf32(float c[4], const unsigned a[4], const unsigned b[2]) {
    asm volatile(
        "mma.sync.aligned.m16n8k8.row.col.f32.tf32.tf32.f32 "
        "{%0,%1,%2,%3}, {%4,%5,%6,%7}, {%8,%9}, {%0,%1,%2,%3};"
        : "+f"(c[0]), "+f"(c[1]), "+f"(c[2]), "+f"(c[3])
        : "r"(a[0]), "r"(a[1]), "r"(a[2]), "r"(a[3]), "r"(b[0]), "r"(b[1]));
}

// ldmatrix x4 on row-major 32-bit data: yields exactly the tf32 m16n8k8 A frag
__device__ __forceinline__ void ldsm_x4(unsigned r[4], unsigned addr) {
    asm volatile("ldmatrix.sync.aligned.m8n8.x4.shared.b16 {%0,%1,%2,%3}, [%4];"
                 : "=r"(r[0]), "=r"(r[1]), "=r"(r[2]), "=r"(r[3]) : "r"(addr));
}

__device__ __forceinline__ void cp_async16(unsigned smem_addr, const void* gptr, int src_bytes) {
    asm volatile("cp.async.ca.shared.global [%0], [%1], 16, %2;"
                 :: "r"(smem_addr), "l"(gptr), "r"(src_bytes));
}
__device__ __forceinline__ void cp_commit() {
    asm volatile("cp.async.commit_group;");
}
template <int N>
__device__ __forceinline__ void cp_wait() {
    asm volatile("cp.async.wait_group %0;" :: "n"(N));
}

// Grouped gather-GEMM 128x128 tile, 3-stage cp.async pipeline.
// All operands pre-rounded to tf32 values -> no converts in the mainloop.
// MODE 0: FFN1 (A = g_xt rows, B = g_w1t, epilogue = tf32(gelu(+b1)) -> g_h)
// MODE 1: FFN2 (A = g_h rows,  B = g_w2t, epilogue = w * acc -> g_y)
template <int MODE>
__global__ __launch_bounds__(256, 2) void k_ffn_mma(const float* __restrict__ bias) {
    const int Kdim = (MODE == 0) ? Dv : Hv;
    const int Ndim = (MODE == 0) ? Hv : Dv;
    const float* Aeff = (MODE == 0) ? (const float*)g_xt : (const float*)g_h;
    const float* Beff = (MODE == 0) ? (const float*)g_w1t : (const float*)g_w2t;

    extern __shared__ char dynsmem[];
    __shared__ int sa[BM];

    int e = blockIdx.z;
    int cnt = g_count[e];
    int m0 = blockIdx.x * BM;
    if (m0 >= cnt) return;
    int n0 = blockIdx.y * BN;

    int tid = threadIdx.x;
    if (tid < BM) sa[tid] = (m0 + tid < cnt) ? g_list[e * Tv + m0 + tid] : -1;
    __syncthreads();

    // ---- loader indices ----
    int ar = tid >> 3;            // A row base (0..31), rows ar+32p
    int ak = (tid & 7) * 4;       // A k offset (0..28)
    const float* aptr[4];
    int asz[4];
#pragma unroll
    for (int p = 0; p < 4; p++) {
        int r = ar + 32 * p;
        int a = sa[r];
        if (a >= 0) {
            int sr = (MODE == 0) ? (a >> 1) : a;    // token vs assignment row
            aptr[p] = Aeff + (size_t)sr * Kdim + ak;
            asz[p] = 16;
        } else { aptr[p] = Aeff; asz[p] = 0; }      // zero-fill, src unread
    }
    int bn = (tid & 31) * 4;      // B n offset (coalesced, conflict-free STS)
    int bkr = tid >> 5;           // B k row base (0..7), rows bkr+8p
    const float* bbase = Beff + (size_t)e * Kdim * Ndim + n0 + bn;

    unsigned smemBase = (unsigned)__cvta_generic_to_shared(dynsmem);
    unsigned aStoreOff[4];
#pragma unroll
    for (int p = 0; p < 4; p++) aStoreOff[p] = ((ar + 32 * p) * LDAW + ak) * 4;
    unsigned bStoreOff[4];
#pragma unroll
    for (int p = 0; p < 4; p++) bStoreOff[p] = STAGE_A_BYTES + ((bkr + 8 * p) * LDBW + bn) * 4;

    // ---- fragment indices ----
    int warp = tid >> 5, lane = tid & 31;
    int wm = (warp >> 2) * 64;    // 0 or 64
    int wn = (warp & 3) * 32;     // 0,32,64,96
    int g = lane >> 2, t = lane & 3;
    int lrow = (lane & 7) + ((lane >> 3) & 1) * 8;   // 0..15
    int lkadd = (lane >> 4) * 4;                     // 0 or 4
    unsigned aFragOff = ((wm + lrow) * LDAW + lkadd) * 4;

    float c[4][4][4];
#pragma unroll
    for (int mt = 0; mt < 4; mt++)
#pragma unroll
        for (int nt = 0; nt < 4; nt++)
#pragma unroll
            for (int i = 0; i < 4; i++) c[mt][nt][i] = 0.f;

    const int nslab = Kdim / BK;

    // prologue: issue stages 0 and 1
#pragma unroll
    for (int s = 0; s < 2; s++) {
        unsigned sb = smemBase + s * STAGE_BYTES;
        int k0 = s * BK;
#pragma unroll
        for (int p = 0; p < 4; p++) cp_async16(sb + aStoreOff[p], aptr[p] + k0, asz[p]);
#pragma unroll
        for (int p = 0; p < 4; p++)
            cp_async16(sb + bStoreOff[p], bbase + (size_t)(k0 + bkr + 8 * p) * Ndim, 16);
        cp_commit();
    }

    for (int i = 0; i < nslab; i++) {
        if (i + 1 < nslab) cp_wait<1>(); else cp_wait<0>();
        __syncthreads();   // stage i ready; all warps done with buffer (i+2)%3

        // issue stage i+2 into buffer (i+2)%3 (its old data computed at i-1)
        if (i + 2 < nslab) {
            int k0 = (i + 2) * BK;
            unsigned sb = smemBase + ((i + 2) % NSTAGE) * STAGE_BYTES;
#pragma unroll
            for (int p = 0; p < 4; p++) cp_async16(sb + aStoreOff[p], aptr[p] + k0, asz[p]);
#pragma unroll
            for (int p = 0; p < 4; p++)
                cp_async16(sb + bStoreOff[p], bbase + (size_t)(k0 + bkr + 8 * p) * Ndim, 16);
            cp_commit();
        }

        // compute on stage i (no converts: operands are tf32-valued bits)
        unsigned sb = smemBase + (i % NSTAGE) * STAGE_BYTES;
        const unsigned* BsT = (const unsigned*)(dynsmem + (i % NSTAGE) * STAGE_BYTES + STAGE_A_BYTES);
#pragma unroll
        for (int ks = 0; ks < 4; ks++) {
            int kk = ks * 8;
            unsigned af[4][4];
#pragma unroll
            for (int mt = 0; mt < 4; mt++)
                ldsm_x4(af[mt], sb + aFragOff + (mt * 16 * LDAW + kk) * 4);
            unsigned bf[4][2];
#pragma unroll
            for (int nt = 0; nt < 4; nt++) {
                int n = wn + nt * 8 + g;
                bf[nt][0] = BsT[(kk + t) * LDBW + n];
                bf[nt][1] = BsT[(kk + t + 4) * LDBW + n];
            }
#pragma unroll
            for (int mt = 0; mt < 4; mt++)
#pragma unroll
                for (int nt = 0; nt < 4; nt++)
                    mma_tf32(c[mt][nt], af[mt], bf[nt]);
        }
    }

    // Epilogue
#pragma unroll
    for (int mt = 0; mt < 4; mt++) {
#pragma unroll
        for (int i = 0; i < 2; i++) {
            int row = wm + mt * 16 + g + i * 8;
            int a = sa[row];
            if (a < 0) continue;
            if (MODE == 0) {
#pragma unroll
                for (int nt = 0; nt < 4; nt++) {
                    int col = n0 + wn + nt * 8 + t * 2;
                    const float* br = bias + (size_t)e * Hv + col;
                    float2 o;   // store tf32-rounded so FFN2 needs no converts
                    o.x = f2tf_f(gelu_tanh(c[mt][nt][i * 2 + 0] + br[0]));
                    o.y = f2tf_f(gelu_tanh(c[mt][nt][i * 2 + 1] + br[1]));
                    *(float2*)&g_h[(size_t)a * Hv + col] = o;
                }
            } else {
                float w = g_w[a];
#pragma unroll
                for (int nt = 0; nt < 4; nt++) {
                    int col = n0 + wn + nt * 8 + t * 2;
                    float2 o;
                    o.x = w * c[mt][nt][i * 2 + 0];
                    o.y = w * c[mt][nt][i * 2 + 1];
                    *(float2*)&g_y[(size_t)a * Dv + col] = o;
                }
            }
        }
    }
}

// Combine: out[t] = y[2t] + y[2t+1] + w0*b2[e0] + w1*b2[e1]
__global__ void k_comb(const float* __restrict__ b2, float* __restrict__ out) {
    int idx = blockIdx.x * blockDim.x + threadIdx.x;   // over T*D/4
    int t = idx / (Dv / 4);
    int c = idx % (Dv / 4);
    int e0 = g_exp[2 * t], e1 = g_exp[2 * t + 1];
    float w0 = g_w[2 * t], w1 = g_w[2 * t + 1];
    float4 y0 = *(const float4*)&g_y[(size_t)(2 * t) * Dv + c * 4];
    float4 y1 = *(const float4*)&g_y[(size_t)(2 * t + 1) * Dv + c * 4];
    float4 bb0 = *(const float4*)&b2[(size_t)e0 * Dv + c * 4];
    float4 bb1 = *(const float4*)&b2[(size_t)e1 * Dv + c * 4];
    float4 o;
    o.x = y0.x + y1.x + w0 * bb0.x + w1 * bb1.x;
    o.y = y0.y + y1.y + w0 * bb0.y + w1 * bb1.y;
    o.z = y0.z + y1.z + w0 * bb0.z + w1 * bb1.z;
    o.w = y0.w + y1.w + w0 * bb0.w + w1 * bb1.w;
    *(float4*)&out[(size_t)t * Dv + c * 4] = o;
}

extern "C" void kernel_launch(void* const* d_in, const int* in_sizes, int n_in,
                              void* d_out, int out_size) {
    const float* x = (const float*)d_in[0];
    int base = (n_in >= 8 && in_sizes[1] == 1) ? 2 : 1;
    const float* Wg = (const float*)d_in[base + 0];
    const float* bg = (const float*)d_in[base + 1];
    const float* W1 = (const float*)d_in[base + 2];
    const float* b1 = (const float*)d_in[base + 3];
    const float* W2 = (const float*)d_in[base + 4];
    const float* b2 = (const float*)d_in[base + 5];

    cudaFuncSetAttribute(k_ffn_mma<0>, cudaFuncAttributeMaxDynamicSharedMemorySize, SMEM_TOTAL);
    cudaFuncSetAttribute(k_ffn_mma<1>, cudaFuncAttributeMaxDynamicSharedMemorySize, SMEM_TOTAL);

    float* xt; cudaGetSymbolAddress((void**)&xt, g_xt);
    float* w1t; cudaGetSymbolAddress((void**)&w1t, g_w1t);
    float* w2t; cudaGetSymbolAddress((void**)&w2t, g_w2t);

    k_zero<<<1, 32>>>();
    k_cvt<<<(Tv * Dv / 4) / 256, 256>>>(x, xt);
    k_cvt<<<(Ev * Dv * Hv / 4) / 256, 256>>>(W1, w1t);
    k_cvt<<<(Ev * Hv * Dv / 4) / 256, 256>>>(W2, w2t);
    k_gate<<<Tv / 8, 256>>>(x, Wg, bg);
    k_ffn_mma<0><<<dim3(Tv / BM, Hv / BN, Ev), 256, SMEM_TOTAL>>>(b1);
    k_ffn_mma<1><<<dim3(Tv / BM, Dv / BN, Ev), 256, SMEM_TOTAL>>>(b1);
    k_comb<<<(Tv * Dv / 4) / 256, 256>>>(b2, (float*)d_out);
}

// round 14
// speedup vs baseline: 1.0017x; 1.0017x over previous
#include <cuda_runtime.h>
#include <math.h>

// Problem constants
#define Bv 4
#define Sv 2048
#define Dv 1024
#define Ev 8
#define Hv 2048
#define Tv (Bv*Sv)        // 8192 tokens
#define Av (2*Tv)         // 16384 assignments (top_k = 2)

// GEMM tiling
#define BM 128
#define BN 128
#define BK 32
#define LDAW 36           // words per A row (144B, conflict-free ldmatrix)
#define LDBW 136          // words per B row (mod 32 == 8 -> conflict-free frag LDS)
#define NSTAGE 3
#define NTHREADS 512

#define STAGE_A_BYTES (BM*LDAW*4)              // 18432
#define STAGE_B_BYTES (BK*LDBW*4)              // 17408
#define STAGE_BYTES   (STAGE_A_BYTES + STAGE_B_BYTES)  // 35840
#define SMEM_TOTAL    (NSTAGE*STAGE_BYTES)     // 107520

// Device scratch (static allocations; no cudaMalloc allowed)
__device__ int   g_count[Ev];
__device__ int   g_list[Ev*Tv];           // assignment ids per expert
__device__ int   g_exp[Av];               // expert per assignment
__device__ float g_w[Av];                 // combine weight per assignment
__device__ float g_h[(size_t)Av*Hv];      // tf32-rounded gelu(FFN1), 134 MB
__device__ float g_y[(size_t)Av*Dv];      // weighted FFN2 outputs, 67 MB
__device__ float g_xt[(size_t)Tv*Dv];     // tf32-rounded x, 32 MB

__global__ void k_zero() {
    if (threadIdx.x < Ev) g_count[threadIdx.x] = 0;
}

__device__ __forceinline__ float f2tf_f(float f) {
    unsigned u;
    asm("cvt.rna.tf32.f32 %0, %1;" : "=r"(u) : "f"(f));
    return __uint_as_float(u);
}
__device__ __forceinline__ unsigned f2tf_u(unsigned raw) {
    unsigned u;
    asm("cvt.rna.tf32.f32 %0, %1;" : "=r"(u) : "f"(__uint_as_float(raw)));
    return u;
}

// Round fp32 array to tf32-valued fp32 (x only; 19us measured).
__global__ void k_cvt(const float* __restrict__ src, float* __restrict__ dst) {
    int i = blockIdx.x * blockDim.x + threadIdx.x;
    float4 v = ((const float4*)src)[i];
    v.x = f2tf_f(v.x); v.y = f2tf_f(v.y); v.z = f2tf_f(v.z); v.w = f2tf_f(v.w);
    ((float4*)dst)[i] = v;
}

// Gating: one warp per token (proven).
__global__ void k_gate(const float* __restrict__ x,
                       const float* __restrict__ Wg,
                       const float* __restrict__ bg) {
    int warp = threadIdx.x >> 5, lane = threadIdx.x & 31;
    int t = blockIdx.x * 8 + warp;
    if (t >= Tv) return;
    float acc[Ev];
#pragma unroll
    for (int e = 0; e < Ev; e++) acc[e] = 0.f;
    const float* xr = x + (size_t)t * Dv;
    for (int d = lane; d < Dv; d += 32) {
        float xv = xr[d];
        const float* wr = Wg + d * Ev;
#pragma unroll
        for (int e = 0; e < Ev; e++) acc[e] += xv * __ldg(wr + e);
    }
#pragma unroll
    for (int e = 0; e < Ev; e++) {
#pragma unroll
        for (int o = 16; o > 0; o >>= 1)
            acc[e] += __shfl_xor_sync(0xffffffffu, acc[e], o);
    }
    if (lane == 0) {
        float l[Ev];
#pragma unroll
        for (int e = 0; e < Ev; e++) l[e] = acc[e] + bg[e];
        int e0 = 0;
#pragma unroll
        for (int e = 1; e < Ev; e++) if (l[e] > l[e0]) e0 = e;
        int e1 = (e0 == 0) ? 1 : 0;
#pragma unroll
        for (int e = 0; e < Ev; e++) if (e != e0 && l[e] > l[e1]) e1 = e;
        float w0 = 1.f / (1.f + expf(l[e1] - l[e0]));
        float w1 = 1.f - w0;
        int a0 = 2 * t, a1 = 2 * t + 1;
        g_exp[a0] = e0; g_exp[a1] = e1;
        g_w[a0] = w0;   g_w[a1] = w1;
        int s0 = atomicAdd(&g_count[e0], 1); g_list[e0 * Tv + s0] = a0;
        int s1 = atomicAdd(&g_count[e1], 1); g_list[e1 * Tv + s1] = a1;
    }
}

__device__ __forceinline__ float gelu_tanh(float v) {
    float u = 0.7978845608028654f * (v + 0.044715f * v * v * v);
    float th;
    asm("tanh.approx.f32 %0, %1;" : "=f"(th) : "f"(u));
    return 0.5f * v * (1.f + th);
}

__device__ __forceinline__ void mma_tf32(float c[4], const unsigned a[4], const unsigned b[2]) {
    asm volatile(
        "mma.sync.aligned.m16n8k8.row.col.f32.tf32.tf32.f32 "
        "{%0,%1,%2,%3}, {%4,%5,%6,%7}, {%8,%9}, {%0,%1,%2,%3};"
        : "+f"(c[0]), "+f"(c[1]), "+f"(c[2]), "+f"(c[3])
        : "r"(a[0]), "r"(a[1]), "r"(a[2]), "r"(a[3]), "r"(b[0]), "r"(b[1]));
}

// ldmatrix x4 on row-major 32-bit data -> tf32 m16n8k8 A fragment
__device__ __forceinline__ void ldsm_x4(unsigned r[4], unsigned addr) {
    asm volatile("ldmatrix.sync.aligned.m8n8.x4.shared.b16 {%0,%1,%2,%3}, [%4];"
                 : "=r"(r[0]), "=r"(r[1]), "=r"(r[2]), "=r"(r[3]) : "r"(addr));
}

__device__ __forceinline__ void cp_async16(unsigned smem_addr, const void* gptr, int src_bytes) {
    asm volatile("cp.async.cg.shared.global [%0], [%1], 16, %2;"
                 :: "r"(smem_addr), "l"(gptr), "r"(src_bytes));
}
__device__ __forceinline__ void cp_commit() { asm volatile("cp.async.commit_group;"); }
template <int N>
__device__ __forceinline__ void cp_wait() { asm volatile("cp.async.wait_group %0;" :: "n"(N)); }

// Grouped gather-GEMM 128x128 tile, 512 threads (warp tile 32x32), 3-stage cp.async.
// A operands are pre-rounded tf32 values (g_xt / g_h); B converts fragment-side.
// MODE 0: FFN1 (A = g_xt token rows, epilogue = tf32(gelu(+b1)) -> g_h)
// MODE 1: FFN2 (A = g_h rows, epilogue = w * acc -> g_y)
template <int MODE>
__global__ __launch_bounds__(NTHREADS, 2) void k_ffn_mma(const float* __restrict__ Bsrc,
                                                         const float* __restrict__ bias) {
    const int Kdim = (MODE == 0) ? Dv : Hv;
    const int Ndim = (MODE == 0) ? Hv : Dv;
    const float* Aeff = (MODE == 0) ? (const float*)g_xt : (const float*)g_h;

    extern __shared__ char dynsmem[];
    __shared__ int sa[BM];

    int e = blockIdx.z;
    int cnt = g_count[e];
    int m0 = blockIdx.x * BM;
    if (m0 >= cnt) return;
    int n0 = blockIdx.y * BN;

    int tid = threadIdx.x;
    if (tid < BM) sa[tid] = (m0 + tid < cnt) ? g_list[e * Tv + m0 + tid] : -1;
    __syncthreads();

    // ---- loader indices (512 threads) ----
    int ar = tid >> 2;            // A row 0..127
    int ak = (tid & 3) * 8;       // A k word offset 0,8,16,24 (2x16B chunks)
    const float* arow;
    int asz;
    {
        int a = sa[ar];
        if (a >= 0) {
            int sr = (MODE == 0) ? (a >> 1) : a;
            arow = Aeff + (size_t)sr * Kdim + ak;
            asz = 16;
        } else { arow = Aeff; asz = 0; }
    }
    int bk = tid >> 4;            // B k row 0..31
    int bn = (tid & 15) * 8;      // B n word offset (2x16B chunks)
    const float* brow = Bsrc + (size_t)e * Kdim * Ndim + (size_t)bk * Ndim + n0 + bn;

    unsigned smemBase = (unsigned)__cvta_generic_to_shared(dynsmem);
    unsigned aOff = (ar * LDAW + ak) * 4;
    unsigned bOff = STAGE_A_BYTES + (bk * LDBW + bn) * 4;

    // ---- fragment indices: warp grid 4x4, warp tile 32x32 ----
    int warp = tid >> 5, lane = tid & 31;
    int wm = (warp >> 2) * 32;    // 0,32,64,96
    int wn = (warp & 3) * 32;     // 0,32,64,96
    int g = lane >> 2, t = lane & 3;
    int lrow = (lane & 7) + ((lane >> 3) & 1) * 8;   // 0..15
    int lkadd = (lane >> 4) * 4;                     // 0 or 4
    unsigned aFragOff = ((wm + lrow) * LDAW + lkadd) * 4;

    float c[2][4][4];
#pragma unroll
    for (int mt = 0; mt < 2; mt++)
#pragma unroll
        for (int nt = 0; nt < 4; nt++)
#pragma unroll
            for (int i = 0; i < 4; i++) c[mt][nt][i] = 0.f;

    const int nslab = Kdim / BK;

    // prologue: issue stages 0 and 1
#pragma unroll
    for (int s = 0; s < 2; s++) {
        unsigned sb = smemBase + s * STAGE_BYTES;
        int k0 = s * BK;
        cp_async16(sb + aOff, arow + k0, asz);
        cp_async16(sb + aOff + 16, arow + k0 + 4, asz);
        cp_async16(sb + bOff, brow + (size_t)k0 * Ndim, 16);
        cp_async16(sb + bOff + 16, brow + (size_t)k0 * Ndim + 4, 16);
        cp_commit();
    }

    for (int i = 0; i < nslab; i++) {
        if (i + 1 < nslab) cp_wait<1>(); else cp_wait<0>();
        __syncthreads();   // stage i ready; buffer (i+2)%3 free

        if (i + 2 < nslab) {
            int k0 = (i + 2) * BK;
            unsigned sb = smemBase + ((i + 2) % NSTAGE) * STAGE_BYTES;
            cp_async16(sb + aOff, arow + k0, asz);
            cp_async16(sb + aOff + 16, arow + k0 + 4, asz);
            cp_async16(sb + bOff, brow + (size_t)k0 * Ndim, 16);
            cp_async16(sb + bOff + 16, brow + (size_t)k0 * Ndim + 4, 16);
            cp_commit();
        }

        unsigned sb = smemBase + (i % NSTAGE) * STAGE_BYTES;
        const unsigned* BsT = (const unsigned*)(dynsmem + (i % NSTAGE) * STAGE_BYTES + STAGE_A_BYTES);
#pragma unroll
        for (int ks = 0; ks < 4; ks++) {
            int kk = ks * 8;
            unsigned af[2][4];
#pragma unroll
            for (int mt = 0; mt < 2; mt++)
                ldsm_x4(af[mt], sb + aFragOff + (mt * 16 * LDAW + kk) * 4);
            unsigned bf[4][2];
#pragma unroll
            for (int nt = 0; nt < 4; nt++) {
                int n = wn + nt * 8 + g;
                bf[nt][0] = f2tf_u(BsT[(kk + t) * LDBW + n]);
                bf[nt][1] = f2tf_u(BsT[(kk + t + 4) * LDBW + n]);
            }
#pragma unroll
            for (int mt = 0; mt < 2; mt++)
#pragma unroll
                for (int nt = 0; nt < 4; nt++)
                    mma_tf32(c[mt][nt], af[mt], bf[nt]);
        }
    }

    // Epilogue
#pragma unroll
    for (int mt = 0; mt < 2; mt++) {
#pragma unroll
        for (int i = 0; i < 2; i++) {
            int row = wm + mt * 16 + g + i * 8;
            int a = sa[row];
            if (a < 0) continue;
            if (MODE == 0) {
#pragma unroll
                for (int nt = 0; nt < 4; nt++) {
                    int col = n0 + wn + nt * 8 + t * 2;
                    const float* br = bias + (size_t)e * Hv + col;
                    float2 o;   // store tf32-rounded so FFN2's A needs no converts
                    o.x = f2tf_f(gelu_tanh(c[mt][nt][i * 2 + 0] + br[0]));
                    o.y = f2tf_f(gelu_tanh(c[mt][nt][i * 2 + 1] + br[1]));
                    *(float2*)&g_h[(size_t)a * Hv + col] = o;
                }
            } else {
                float w = g_w[a];
#pragma unroll
                for (int nt = 0; nt < 4; nt++) {
                    int col = n0 + wn + nt * 8 + t * 2;
                    float2 o;
                    o.x = w * c[mt][nt][i * 2 + 0];
                    o.y = w * c[mt][nt][i * 2 + 1];
                    *(float2*)&g_y[(size_t)a * Dv + col] = o;
                }
            }
        }
    }
}

// Combine: out[t] = y[2t] + y[2t+1] + w0*b2[e0] + w1*b2[e1]
__global__ void k_comb(const float* __restrict__ b2, float* __restrict__ out) {
    int idx = blockIdx.x * blockDim.x + threadIdx.x;   // over T*D/4
    int t = idx / (Dv / 4);
    int c = idx % (Dv / 4);
    int e0 = g_exp[2 * t], e1 = g_exp[2 * t + 1];
    float w0 = g_w[2 * t], w1 = g_w[2 * t + 1];
    float4 y0 = *(const float4*)&g_y[(size_t)(2 * t) * Dv + c * 4];
    float4 y1 = *(const float4*)&g_y[(size_t)(2 * t + 1) * Dv + c * 4];
    float4 bb0 = *(const float4*)&b2[(size_t)e0 * Dv + c * 4];
    float4 bb1 = *(const float4*)&b2[(size_t)e1 * Dv + c * 4];
    float4 o;
    o.x = y0.x + y1.x + w0 * bb0.x + w1 * bb1.x;
    o.y = y0.y + y1.y + w0 * bb0.y + w1 * bb1.y;
    o.z = y0.z + y1.z + w0 * bb0.z + w1 * bb1.z;
    o.w = y0.w + y1.w + w0 * bb0.w + w1 * bb1.w;
    *(float4*)&out[(size_t)t * Dv + c * 4] = o;
}

extern "C" void kernel_launch(void* const* d_in, const int* in_sizes, int n_in,
                              void* d_out, int out_size) {
    const float* x = (const float*)d_in[0];
    int base = (n_in >= 8 && in_sizes[1] == 1) ? 2 : 1;
    const float* Wg = (const float*)d_in[base + 0];
    const float* bg = (const float*)d_in[base + 1];
    const float* W1 = (const float*)d_in[base + 2];
    const float* b1 = (const float*)d_in[base + 3];
    const float* W2 = (const float*)d_in[base + 4];
    const float* b2 = (const float*)d_in[base + 5];

    cudaFuncSetAttribute(k_ffn_mma<0>, cudaFuncAttributeMaxDynamicSharedMemorySize, SMEM_TOTAL);
    cudaFuncSetAttribute(k_ffn_mma<1>, cudaFuncAttributeMaxDynamicSharedMemorySize, SMEM_TOTAL);

    float* xt; cudaGetSymbolAddress((void**)&xt, g_xt);

    k_zero<<<1, 32>>>();
    k_cvt<<<(Tv * Dv / 4) / 256, 256>>>(x, xt);
    k_gate<<<Tv / 8, 256>>>(x, Wg, bg);
    k_ffn_mma<0><<<dim3(Tv / BM, Hv / BN, Ev), NTHREADS, SMEM_TOTAL>>>(W1, b1);
    k_ffn_mma<1><<<dim3(Tv / BM, Dv / BN, Ev), NTHREADS, SMEM_TOTAL>>>(W2, b1);
    k_comb<<<(Tv * Dv / 4) / 256, 256>>>(b2, (float*)d_out);
}